// round 17
// baseline (speedup 1.0000x reference)
#include <cuda_runtime.h>

#define SEQ    262144
#define HID    20
#define INP    9
#define CH     112
#define WARM   32
#define GROUP  16
#define HB     32               // h2 staging depth (2 groups)
#define HBP    22               // padded row
#define NCHUNK ((SEQ + CH - 1) / CH)     // 2341
#define NBLK   ((NCHUNK + 7) / 8)        // 293 blocks * 4 warps * 2 chunks

typedef unsigned int u32;

__device__ __forceinline__ u32 pkh2(float lo, float hi) {
    u32 r; asm("cvt.rn.f16x2.f32 %0,%1,%2;" : "=r"(r) : "f"(hi), "f"(lo)); return r;
}
__device__ __forceinline__ void uph2(u32 v, float& lo, float& hi) {
    asm("{.reg .f16 l,h; mov.b32 {l,h},%2; cvt.f32.f16 %0,l; cvt.f32.f16 %1,h;}"
        : "=f"(lo), "=f"(hi) : "r"(v));
}
__device__ __forceinline__ u32 h2fma(u32 a, u32 b, u32 c) {
    u32 d; asm("fma.rn.f16x2 %0,%1,%2,%3;" : "=r"(d) : "r"(a), "r"(b), "r"(c)); return d;
}
__device__ __forceinline__ float tanha(float v) {
    float r; asm("tanh.approx.f32 %0,%1;" : "=f"(r) : "f"(v)); return r;
}
__device__ __forceinline__ float sigf(float v) {
    return fmaf(0.5f, tanha(0.5f * v), 0.5f);
}

__global__ void __launch_bounds__(128, 2) lstm_kernel(
    const float* __restrict__ x,
    const float* __restrict__ w_ih1, const float* __restrict__ w_hh1, const float* __restrict__ b1,
    const float* __restrict__ w_ih2, const float* __restrict__ w_hh2, const float* __restrict__ b2,
    const float* __restrict__ w_p,  const float* __restrict__ b_p,
    float* __restrict__ out)
{
    __shared__ __align__(16) float xbuf[4][2][2][GROUP * INP];  // [warp][cc][dbl]
    __shared__ __align__(16) float hgrp[4][2][HB][HBP];         // [warp][cc] h2 staging

    const int warp = threadIdx.x >> 5;
    const int lane = threadIdx.x & 31;
    const int cbase = (blockIdx.x * 4 + warp) * 2;
    const int k    = (lane < HID) ? lane : (HID - 1);
    const bool active = (lane < HID);

    int ob[2], oe[2], st[2], ng[2];
    #pragma unroll
    for (int cc = 0; cc < 2; cc++) {
        const int chunk = cbase + cc;
        if (chunk < NCHUNK) {
            ob[cc] = chunk * CH;
            oe[cc] = (ob[cc] + CH < SEQ) ? (ob[cc] + CH) : SEQ;
            st[cc] = (chunk == 0) ? 0 : (ob[cc] - WARM);
            ng[cc] = (oe[cc] - st[cc]) >> 4;
        } else { ob[cc] = 0; oe[cc] = 0; st[cc] = 0; ng[cc] = 0; }
    }
    const int ngmax = (ng[0] > ng[1]) ? ng[0] : ng[1];
    if (ngmax == 0) return;

    // ---- weights (shared by both chunks) ----
    u32   wi1h[4][5];
    u32   whh1h[4][HID / 2];
    u32   wi2h[4][HID / 2];
    u32   whh2h[4][HID / 2];
    float bb1[4], bb2[4];
    #pragma unroll
    for (int g = 0; g < 4; g++) {
        const int r1 = g * HID + k;
        #pragma unroll
        for (int q = 0; q < 4; q++)
            wi1h[g][q] = pkh2(w_ih1[r1 * INP + 2 * q], w_ih1[r1 * INP + 2 * q + 1]);
        wi1h[g][4] = pkh2(w_ih1[r1 * INP + 8], 0.f);
        bb1[g] = b1[r1];
        bb2[g] = b2[r1];
        #pragma unroll
        for (int j = 0; j < HID / 2; j++) {
            whh1h[g][j] = pkh2(w_hh1[r1 * HID + 2 * j], w_hh1[r1 * HID + 2 * j + 1]);
            wi2h[g][j]  = pkh2(w_ih2[r1 * HID + 2 * j], w_ih2[r1 * HID + 2 * j + 1]);
            whh2h[g][j] = pkh2(w_hh2[r1 * HID + 2 * j], w_hh2[r1 * HID + 2 * j + 1]);
        }
    }
    const float bp = b_p[0];

    float h1v[2] = {0.f, 0.f}, c1[2] = {0.f, 0.f};
    float h2v[2] = {0.f, 0.f}, c2[2] = {0.f, 0.f};
    u32 h1pair[2] = {0u, 0u}, h2pair[2] = {0u, 0u};

    auto stagex = [&](int cc, int xg) {
        const float4* src = (const float4*)(x + (st[cc] + (xg << 4)) * INP);
        float4* dst = (float4*)&xbuf[warp][cc][xg & 1][0];
        dst[lane] = src[lane];
        if (lane < 4) dst[32 + lane] = src[32 + lane];
    };

    auto outproj = [&](int cc, int g) {
        if (lane < GROUP) {
            const int sg = (g << 4) + lane;
            const int t = st[cc] + sg;
            if (t >= ob[cc] && t < oe[cc]) {
                const float* hp = &hgrp[warp][cc][sg & (HB - 1)][0];
                float p = bp;
                #pragma unroll
                for (int j = 0; j < HID; j++) p = fmaf(hp[j], __ldg(&w_p[j]), p);
                out[t] = p;
            }
        }
    };

    #pragma unroll
    for (int cc = 0; cc < 2; cc++) if (ng[cc] > 0) stagex(cc, 0);
    __syncwarp();

    for (int g = 0; g < ngmax; g++) {
        #pragma unroll
        for (int cc = 0; cc < 2; cc++) if (g + 1 < ng[cc]) stagex(cc, g + 1);
        __syncwarp();

        #pragma unroll 1
        for (int i16 = 0; i16 < GROUP; i16++) {
            const int i = (g << 4) + i16;
            #pragma unroll
            for (int cc = 0; cc < 2; cc++) {
                if (g >= ng[cc]) continue;
                const float* xb = &xbuf[warp][cc][g & 1][i16 * INP];

                float xv[INP];
                #pragma unroll
                for (int j = 0; j < INP; j++) xv[j] = xb[j];
                u32 px[5];
                #pragma unroll
                for (int q = 0; q < 4; q++) px[q] = pkh2(xv[2 * q], xv[2 * q + 1]);
                px[4] = pkh2(xv[8], 0.f);

                // layer1 x-projection
                u32 a1[4] = {0u, 0u, 0u, 0u};
                #pragma unroll
                for (int q = 0; q < 5; q++) {
                    #pragma unroll
                    for (int gt = 0; gt < 4; gt++) a1[gt] = h2fma(px[q], wi1h[gt][q], a1[gt]);
                }

                // shared broadcast of h1[i-1]: layer1 recurrence + layer2 input
                u32 a2i[4] = {0u, 0u, 0u, 0u};
                u32 a2h[4] = {0u, 0u, 0u, 0u};
                #pragma unroll
                for (int j = 0; j < HID / 2; j++) {
                    const u32 b1j = __shfl_sync(0xffffffffu, h1pair[cc], 2 * j);
                    const u32 b2j = __shfl_sync(0xffffffffu, h2pair[cc], 2 * j);
                    #pragma unroll
                    for (int gt = 0; gt < 4; gt++) {
                        a1[gt]  = h2fma(b1j, whh1h[gt][j], a1[gt]);
                        a2i[gt] = h2fma(b1j, wi2h[gt][j],  a2i[gt]);
                        a2h[gt] = h2fma(b2j, whh2h[gt][j], a2h[gt]);
                    }
                }

                // layer1 gates -> h1[i]
                float pa1[4];
                #pragma unroll
                for (int gt = 0; gt < 4; gt++) {
                    float lo, hi; uph2(a1[gt], lo, hi);
                    pa1[gt] = bb1[gt] + (lo + hi);
                }
                {
                    const float ig = sigf(pa1[0]);
                    const float fg = sigf(pa1[1]);
                    const float gg = tanha(pa1[2]);
                    const float og = sigf(pa1[3]);
                    c1[cc] = fg * c1[cc] + ig * gg;
                    h1v[cc] = og * tanha(c1[cc]);
                }

                // layer2 gates -> h2[i-1]
                float pa2[4];
                #pragma unroll
                for (int gt = 0; gt < 4; gt++) {
                    float lo1, hi1, lo2, hi2;
                    uph2(a2i[gt], lo1, hi1);
                    uph2(a2h[gt], lo2, hi2);
                    pa2[gt] = bb2[gt] + (lo1 + hi1) + (lo2 + hi2);
                }
                {
                    const float ig = sigf(pa2[0]);
                    const float fg = sigf(pa2[1]);
                    const float gg = tanha(pa2[2]);
                    const float og = sigf(pa2[3]);
                    c2[cc] = fg * c2[cc] + ig * gg;
                    h2v[cc] = og * tanha(c2[cc]);
                }

                if (active) hgrp[warp][cc][(i - 1) & (HB - 1)][k] = h2v[cc];

                const float h1n = __shfl_down_sync(0xffffffffu, h1v[cc], 1);
                h1pair[cc] = pkh2(h1v[cc], h1n);
                const float h2n = __shfl_down_sync(0xffffffffu, h2v[cc], 1);
                h2pair[cc] = pkh2(h2v[cc], h2n);

                if (i == 0) { h2v[cc] = 0.f; c2[cc] = 0.f; h2pair[cc] = 0u; }
            }
        }

        if (g >= 1) {
            __syncwarp();
            #pragma unroll
            for (int cc = 0; cc < 2; cc++)
                if (g - 1 < ng[cc]) outproj(cc, g - 1);
        }
    }

    // epilogue: per chunk, final layer2 step + last group's outputs
    #pragma unroll
    for (int cc = 0; cc < 2; cc++) {
        if (ng[cc] == 0) continue;
        u32 a2i[4] = {0u, 0u, 0u, 0u};
        u32 a2h[4] = {0u, 0u, 0u, 0u};
        #pragma unroll
        for (int j = 0; j < HID / 2; j++) {
            const u32 b1j = __shfl_sync(0xffffffffu, h1pair[cc], 2 * j);
            const u32 b2j = __shfl_sync(0xffffffffu, h2pair[cc], 2 * j);
            #pragma unroll
            for (int gt = 0; gt < 4; gt++) {
                a2i[gt] = h2fma(b1j, wi2h[gt][j],  a2i[gt]);
                a2h[gt] = h2fma(b2j, whh2h[gt][j], a2h[gt]);
            }
        }
        float pa2[4];
        #pragma unroll
        for (int gt = 0; gt < 4; gt++) {
            float lo1, hi1, lo2, hi2;
            uph2(a2i[gt], lo1, hi1);
            uph2(a2h[gt], lo2, hi2);
            pa2[gt] = bb2[gt] + (lo1 + hi1) + (lo2 + hi2);
        }
        const float ig = sigf(pa2[0]);
        const float fg = sigf(pa2[1]);
        const float gg = tanha(pa2[2]);
        const float og = sigf(pa2[3]);
        c2[cc] = fg * c2[cc] + ig * gg;
        h2v[cc] = og * tanha(c2[cc]);
        const int last = (ng[cc] << 4) - 1;
        if (active) hgrp[warp][cc][last & (HB - 1)][k] = h2v[cc];

        __syncwarp();
        outproj(cc, ng[cc] - 1);
    }
}

extern "C" void kernel_launch(void* const* d_in, const int* in_sizes, int n_in,
                              void* d_out, int out_size)
{
    const float* x     = (const float*)d_in[0];
    const float* w_ih1 = (const float*)d_in[1];
    const float* w_hh1 = (const float*)d_in[2];
    const float* b1    = (const float*)d_in[3];
    const float* w_ih2 = (const float*)d_in[4];
    const float* w_hh2 = (const float*)d_in[5];
    const float* b2    = (const float*)d_in[6];
    const float* w_p   = (const float*)d_in[7];
    const float* b_p   = (const float*)d_in[8];
    float* out = (float*)d_out;

    lstm_kernel<<<NBLK, 128>>>(x, w_ih1, w_hh1, b1, w_ih2, w_hh2, b2, w_p, b_p, out);
}